// round 5
// baseline (speedup 1.0000x reference)
#include <cuda_runtime.h>

#define B_ 16
#define ORDER_ 2
#define N_ 512
#define D_ 128
#define H_ 8
#define DH_ 16
#define NBIC 64   // B*ORDER*2 (b,i,c) combos

// ---------------- scratch (device globals; no allocations) ----------------
__device__ __align__(16) float g_xp  [NBIC * N_ * D_];   // projected features (+pb)
__device__ __align__(16) float g_ssrc[NBIC * N_ * H_];
__device__ __align__(16) float g_sdst[NBIC * N_ * H_];
__device__ __align__(16) float g_att [NBIC * N_ * D_];   // per-conv GAT output (+xp +bias)

// ---------------- packed f32x2 helpers ----------------
__device__ __forceinline__ unsigned long long pk2(float a, float b) {
    unsigned long long r;
    asm("mov.b64 %0, {%1, %2};" : "=l"(r) : "r"(__float_as_uint(a)), "r"(__float_as_uint(b)));
    return r;
}
__device__ __forceinline__ void upk2(unsigned long long v, float& a, float& b) {
    unsigned int lo, hi;
    asm("mov.b64 {%0, %1}, %2;" : "=r"(lo), "=r"(hi) : "l"(v));
    a = __uint_as_float(lo); b = __uint_as_float(hi);
}
__device__ __forceinline__ void fma2(unsigned long long& d, unsigned long long a, unsigned long long b) {
    asm("fma.rn.f32x2 %0, %1, %2, %0;" : "+l"(d) : "l"(a), "l"(b));
}

// ============================================================================
// Kernel 1: projection xp = x @ W^T + pb  (per (b,i,c)),
//           fused epilogue computes ssrc/sdst head dots.
// grid: (8 n-tiles, 64 bic), block 256.  M-tile=64 n, full 128 d, K chunks of 32.
// Thread micro-tile: 8n x 4d (warp = one 8-row n group, lane = d/4).
// ============================================================================
__global__ __launch_bounds__(256) void proj_kernel(
    const float* __restrict__ x, const float* __restrict__ W, const float* __restrict__ pb,
    const float* __restrict__ asrc, const float* __restrict__ adst)
{
    const int bic  = blockIdx.y;
    const int nt   = blockIdx.x;
    const int c    = bic & 1;
    const int bi   = bic >> 1;
    const int iord = bi & 1;
    const int tid  = threadIdx.x;
    const int lane = tid & 31, warp = tid >> 5;

    __shared__ __align__(16) float xs[64][36];    // [n][k] (pad 4)
    __shared__ __align__(16) float wt[32][128];   // [k][d], XOR-swizzled float4 columns

    const float* xb = x + ((size_t)bi * N_ + nt * 64) * D_;
    const float* Wb = W + (size_t)(iord * 2 + c) * D_ * D_;

    unsigned long long acc[8][2];
#pragma unroll
    for (int r = 0; r < 8; r++) { acc[r][0] = 0ull; acc[r][1] = 0ull; }

    for (int kc = 0; kc < 4; kc++) {
        __syncthreads();
        // x tile: 64 x 32 floats = 512 float4
#pragma unroll
        for (int t2 = 0; t2 < 2; t2++) {
            int fid = tid + t2 * 256;
            int s = fid >> 3, kq = fid & 7;
            float4 v = *(const float4*)(xb + (size_t)s * D_ + kc * 32 + kq * 4);
            *(float4*)&xs[s][kq * 4] = v;
        }
        // W tile transpose with XOR swizzle: wt[k][(d4^k)*4 + d%4] = W[d][kc*32+k]
#pragma unroll
        for (int t4 = 0; t4 < 4; t4++) {
            int fid = tid + t4 * 256;
            int d = fid >> 3, kq = fid & 7;
            float4 v = *(const float4*)(Wb + (size_t)d * D_ + kc * 32 + kq * 4);
            int d4 = d >> 2, dr = d & 3;
            wt[kq * 4 + 0][((d4 ^ (kq * 4 + 0)) << 2) + dr] = v.x;
            wt[kq * 4 + 1][((d4 ^ (kq * 4 + 1)) << 2) + dr] = v.y;
            wt[kq * 4 + 2][((d4 ^ (kq * 4 + 2)) << 2) + dr] = v.z;
            wt[kq * 4 + 3][((d4 ^ (kq * 4 + 3)) << 2) + dr] = v.w;
        }
        __syncthreads();
#pragma unroll 4
        for (int k = 0; k < 32; k++) {
            float4 wv = *(const float4*)&wt[k][(lane ^ k) << 2];  // logical d = lane*4..+3
            unsigned long long w01 = pk2(wv.x, wv.y);
            unsigned long long w23 = pk2(wv.z, wv.w);
#pragma unroll
            for (int r = 0; r < 8; r++) {
                float a = xs[warp * 8 + r][k];
                unsigned long long a2 = pk2(a, a);
                fma2(acc[r][0], a2, w01);
                fma2(acc[r][1], a2, w23);
            }
        }
    }

    // epilogue: +pb, store xp, fused head-dot reductions for ssrc/sdst
    const float4 pbv = *(const float4*)(pb + (iord * 2 + c) * D_ + lane * 4);
    const int h  = lane >> 2;
    const int fb = (lane & 3) * 4;
    const float4 av = *(const float4*)(asrc + ((iord * 2 + c) * H_ + h) * DH_ + fb);
    const float4 dv = *(const float4*)(adst + ((iord * 2 + c) * H_ + h) * DH_ + fb);
#pragma unroll
    for (int r = 0; r < 8; r++) {
        int n = nt * 64 + warp * 8 + r;
        float x0, x1, x2, x3;
        upk2(acc[r][0], x0, x1);
        upk2(acc[r][1], x2, x3);
        x0 += pbv.x; x1 += pbv.y; x2 += pbv.z; x3 += pbv.w;
        *(float4*)(g_xp + ((size_t)bic * N_ + n) * D_ + lane * 4) = make_float4(x0, x1, x2, x3);
        float ps = x0 * av.x + x1 * av.y + x2 * av.z + x3 * av.w;
        float pd = x0 * dv.x + x1 * dv.y + x2 * dv.z + x3 * dv.w;
        ps += __shfl_xor_sync(0xffffffffu, ps, 1);
        ps += __shfl_xor_sync(0xffffffffu, ps, 2);
        pd += __shfl_xor_sync(0xffffffffu, pd, 1);
        pd += __shfl_xor_sync(0xffffffffu, pd, 2);
        if ((lane & 3) == 0) {
            g_ssrc[((size_t)bic * N_ + n) * H_ + h] = ps;
            g_sdst[((size_t)bic * N_ + n) * H_ + h] = pd;
        }
    }
}

// ============================================================================
// Kernel 2: attention. grid: (16 dst-tiles, 64 bic), block 256.
// Thread = (dst_local = tid/8, head = tid%8); accumulates DH=16 features
// as 8 packed f32x2 + running softmax denominator Z.
// Non-edges contribute exp(0)=1 (reference masks alpha to 0 pre-softmax).
// ============================================================================
#define TS 32
__global__ __launch_bounds__(256) void att_kernel(
    const int* __restrict__ A, const float* __restrict__ bias)
{
    const int bic  = blockIdx.y;
    const int tile = blockIdx.x;
    const int c    = bic & 1;
    const int bi   = bic >> 1;
    const int iord = bi & 1;
    const int tid  = threadIdx.x;
    const int h  = tid & 7;
    const int dl = tid >> 3;
    const int dst = tile * 32 + dl;

    __shared__ __align__(16) float sm_xh[TS][160];  // head-stride 20 -> conflict-free bcast
    __shared__ __align__(16) float sm_ss[TS][8];
    __shared__ __align__(16) float sm_ae[TS][32];

    const float* xp   = g_xp   + (size_t)bic * N_ * D_;
    const float* ssrc = g_ssrc + (size_t)bic * N_ * H_;
    const float  sd   = g_sdst[(size_t)bic * N_ * H_ + (size_t)dst * H_ + h];
    const int*   Ab   = A + (size_t)bi * N_ * N_ + tile * 32;
    const int    tgt  = 2 + c;   // edge iff A==4 || A==tgt

    unsigned long long acc[8];
#pragma unroll
    for (int j = 0; j < 8; j++) acc[j] = 0ull;
    float Z = 0.0f;

    for (int s0 = 0; s0 < N_; s0 += TS) {
        __syncthreads();
        // xh tile: 32 x 128 floats = 1024 float4, repacked to head-stride-20
#pragma unroll
        for (int k = 0; k < 4; k++) {
            int fid = tid + k * 256;
            int s = fid >> 5, dq = fid & 31;
            float4 v = *(const float4*)(xp + (size_t)(s0 + s) * D_ + dq * 4);
            *(float4*)&sm_xh[s][(dq >> 2) * 20 + (dq & 3) * 4] = v;
        }
        // ssrc tile: 32 x 8 = 64 float4
        if (tid < 64) {
            int s = tid >> 1, part = (tid & 1) * 4;
            *(float4*)&sm_ss[s][part] = *(const float4*)(ssrc + (size_t)(s0 + s) * H_ + part);
        }
        // A tile -> edge floats: 32 x 32 ints = 256 int4 (one per thread)
        {
            int s = tid >> 3, q = tid & 7;
            int4 avv = *(const int4*)(Ab + (size_t)(s0 + s) * N_ + q * 4);
            float4 ef;
            ef.x = (avv.x == 4 || avv.x == tgt) ? 1.0f : 0.0f;
            ef.y = (avv.y == 4 || avv.y == tgt) ? 1.0f : 0.0f;
            ef.z = (avv.z == 4 || avv.z == tgt) ? 1.0f : 0.0f;
            ef.w = (avv.w == 4 || avv.w == tgt) ? 1.0f : 0.0f;
            *(float4*)&sm_ae[s][q * 4] = ef;
        }
        __syncthreads();
#pragma unroll 8
        for (int s = 0; s < TS; s++) {
            float t = sm_ss[s][h] + sd;
            t = fmaxf(t, 0.2f * t);                       // leaky relu
            float ex = __expf(t);
            float e  = fmaf(sm_ae[s][dl], ex - 1.0f, 1.0f); // edge? exp : 1
            Z += e;
            unsigned long long e2 = pk2(e, e);
            const unsigned long long* xv = (const unsigned long long*)&sm_xh[s][h * 20];
#pragma unroll
            for (int j = 0; j < 8; j++) fma2(acc[j], e2, xv[j]);
        }
    }

    // epilogue: /Z, + xp (add_self_loops), + bias
    const float invZ = 1.0f / Z;
    const float* xpd  = xp + (size_t)dst * D_ + h * DH_;
    const float* bb   = bias + (iord * 2 + c) * D_ + h * DH_;
    float*       outp = g_att + (size_t)bic * N_ * D_ + (size_t)dst * D_ + h * DH_;
#pragma unroll
    for (int jj = 0; jj < 4; jj++) {
        float f0, f1, f2, f3;
        upk2(acc[2 * jj],     f0, f1);
        upk2(acc[2 * jj + 1], f2, f3);
        float4 xq = *(const float4*)(xpd + jj * 4);
        float4 bq = *(const float4*)(bb + jj * 4);
        float4 o;
        o.x = f0 * invZ + xq.x + bq.x;
        o.y = f1 * invZ + xq.y + bq.y;
        o.z = f2 * invZ + xq.z + bq.z;
        o.w = f3 * invZ + xq.w + bq.w;
        *(float4*)(outp + jj * 4) = o;
    }
}

// ============================================================================
// Kernel 3: combine.  h[b,i] = att[b,i,0] + att[b,i,1];
//           out[b,i] = h[b,i] + 0.5*(h[b,0] + h[b,1])
// ============================================================================
__global__ void combine_kernel(float4* __restrict__ out) {
    int gid = blockIdx.x * blockDim.x + threadIdx.x;   // 0 .. 16*16384-1
    int b = gid >> 14;
    int r = gid & 16383;
    const float4* a = (const float4*)g_att;
    float4 a00 = a[(size_t)(b * 4 + 0) * 16384 + r];
    float4 a01 = a[(size_t)(b * 4 + 1) * 16384 + r];
    float4 a10 = a[(size_t)(b * 4 + 2) * 16384 + r];
    float4 a11 = a[(size_t)(b * 4 + 3) * 16384 + r];
    float4 h0, h1, o0, o1;
    h0.x = a00.x + a01.x; h0.y = a00.y + a01.y; h0.z = a00.z + a01.z; h0.w = a00.w + a01.w;
    h1.x = a10.x + a11.x; h1.y = a10.y + a11.y; h1.z = a10.z + a11.z; h1.w = a10.w + a11.w;
    float mx = 0.5f * (h0.x + h1.x), my = 0.5f * (h0.y + h1.y);
    float mz = 0.5f * (h0.z + h1.z), mw = 0.5f * (h0.w + h1.w);
    o0.x = h0.x + mx; o0.y = h0.y + my; o0.z = h0.z + mz; o0.w = h0.w + mw;
    o1.x = h1.x + mx; o1.y = h1.y + my; o1.z = h1.z + mz; o1.w = h1.w + mw;
    out[(size_t)(b * 2 + 0) * 16384 + r] = o0;
    out[(size_t)(b * 2 + 1) * 16384 + r] = o1;
}

// ============================================================================
extern "C" void kernel_launch(void* const* d_in, const int* in_sizes, int n_in,
                              void* d_out, int out_size) {
    const float* x    = (const float*)d_in[0];
    const int*   A    = (const int*)  d_in[1];
    const float* W    = (const float*)d_in[2];
    const float* pb   = (const float*)d_in[3];
    const float* asrc = (const float*)d_in[4];
    const float* adst = (const float*)d_in[5];
    const float* bias = (const float*)d_in[6];

    proj_kernel<<<dim3(8, 64), 256>>>(x, W, pb, asrc, adst);
    att_kernel<<<dim3(16, 64), 256>>>(A, bias);
    combine_kernel<<<1024, 256>>>((float4*)d_out);
}

// round 7
// speedup vs baseline: 1.5791x; 1.5791x over previous
#include <cuda_runtime.h>

#define B_ 16
#define ORDER_ 2
#define N_ 512
#define D_ 128
#define H_ 8
#define DH_ 16
#define NBIC 64   // B*ORDER*2 (b,i,c) combos

// ---------------- scratch (device globals; no allocations) ----------------
__device__ __align__(16) float g_xp  [NBIC * N_ * D_];       // projected features (+pb)
__device__ __align__(16) float g_src4[NBIC * N_ * H_ * 4];   // {ssrc, exp(ssrc), exp(.2 ssrc), 0}
__device__ __align__(16) float g_dst4[NBIC * N_ * H_ * 4];   // {sdst, exp(sdst), exp(.2 sdst), 0}
__device__ __align__(16) float g_att [NBIC * N_ * D_];       // per-conv GAT output (+xp +bias)

// ---------------- packed f32x2 helpers ----------------
__device__ __forceinline__ unsigned long long pk2(float a, float b) {
    unsigned long long r;
    asm("mov.b64 %0, {%1, %2};" : "=l"(r) : "r"(__float_as_uint(a)), "r"(__float_as_uint(b)));
    return r;
}
__device__ __forceinline__ void upk2(unsigned long long v, float& a, float& b) {
    unsigned int lo, hi;
    asm("mov.b64 {%0, %1}, %2;" : "=r"(lo), "=r"(hi) : "l"(v));
    a = __uint_as_float(lo); b = __uint_as_float(hi);
}
__device__ __forceinline__ void fma2(unsigned long long& d, unsigned long long a, unsigned long long b) {
    asm("fma.rn.f32x2 %0, %1, %2, %0;" : "+l"(d) : "l"(a), "l"(b));
}

// ============================================================================
// Kernel 1: projection xp = x @ W^T + pb  (per (b,i,c)),
//           fused epilogue computes ssrc/sdst head dots AND their exp forms.
// grid: (8 n-tiles, 64 bic), block 256.
// ============================================================================
__global__ __launch_bounds__(256) void proj_kernel(
    const float* __restrict__ x, const float* __restrict__ W, const float* __restrict__ pb,
    const float* __restrict__ asrc, const float* __restrict__ adst)
{
    const int bic  = blockIdx.y;
    const int nt   = blockIdx.x;
    const int c    = bic & 1;
    const int bi   = bic >> 1;
    const int iord = bi & 1;
    const int tid  = threadIdx.x;
    const int lane = tid & 31, warp = tid >> 5;

    __shared__ __align__(16) float xs[64][36];    // [n][k] (pad 4)
    __shared__ __align__(16) float wt[32][128];   // [k][d], XOR-swizzled float4 columns

    const float* xb = x + ((size_t)bi * N_ + nt * 64) * D_;
    const float* Wb = W + (size_t)(iord * 2 + c) * D_ * D_;

    unsigned long long acc[8][2];
#pragma unroll
    for (int r = 0; r < 8; r++) { acc[r][0] = 0ull; acc[r][1] = 0ull; }

    for (int kc = 0; kc < 4; kc++) {
        __syncthreads();
#pragma unroll
        for (int t2 = 0; t2 < 2; t2++) {
            int fid = tid + t2 * 256;
            int s = fid >> 3, kq = fid & 7;
            float4 v = *(const float4*)(xb + (size_t)s * D_ + kc * 32 + kq * 4);
            *(float4*)&xs[s][kq * 4] = v;
        }
#pragma unroll
        for (int t4 = 0; t4 < 4; t4++) {
            int fid = tid + t4 * 256;
            int d = fid >> 3, kq = fid & 7;
            float4 v = *(const float4*)(Wb + (size_t)d * D_ + kc * 32 + kq * 4);
            int d4 = d >> 2, dr = d & 3;
            wt[kq * 4 + 0][((d4 ^ (kq * 4 + 0)) << 2) + dr] = v.x;
            wt[kq * 4 + 1][((d4 ^ (kq * 4 + 1)) << 2) + dr] = v.y;
            wt[kq * 4 + 2][((d4 ^ (kq * 4 + 2)) << 2) + dr] = v.z;
            wt[kq * 4 + 3][((d4 ^ (kq * 4 + 3)) << 2) + dr] = v.w;
        }
        __syncthreads();
#pragma unroll 4
        for (int k = 0; k < 32; k++) {
            float4 wv = *(const float4*)&wt[k][(lane ^ k) << 2];
            unsigned long long w01 = pk2(wv.x, wv.y);
            unsigned long long w23 = pk2(wv.z, wv.w);
#pragma unroll
            for (int r = 0; r < 8; r++) {
                float a = xs[warp * 8 + r][k];
                unsigned long long a2 = pk2(a, a);
                fma2(acc[r][0], a2, w01);
                fma2(acc[r][1], a2, w23);
            }
        }
    }

    const float4 pbv = *(const float4*)(pb + (iord * 2 + c) * D_ + lane * 4);
    const int h  = lane >> 2;
    const int fb = (lane & 3) * 4;
    const float4 av = *(const float4*)(asrc + ((iord * 2 + c) * H_ + h) * DH_ + fb);
    const float4 dv = *(const float4*)(adst + ((iord * 2 + c) * H_ + h) * DH_ + fb);
#pragma unroll
    for (int r = 0; r < 8; r++) {
        int n = nt * 64 + warp * 8 + r;
        float x0, x1, x2, x3;
        upk2(acc[r][0], x0, x1);
        upk2(acc[r][1], x2, x3);
        x0 += pbv.x; x1 += pbv.y; x2 += pbv.z; x3 += pbv.w;
        *(float4*)(g_xp + ((size_t)bic * N_ + n) * D_ + lane * 4) = make_float4(x0, x1, x2, x3);
        float ps = x0 * av.x + x1 * av.y + x2 * av.z + x3 * av.w;
        float pd = x0 * dv.x + x1 * dv.y + x2 * dv.z + x3 * dv.w;
        ps += __shfl_xor_sync(0xffffffffu, ps, 1);
        ps += __shfl_xor_sync(0xffffffffu, ps, 2);
        pd += __shfl_xor_sync(0xffffffffu, pd, 1);
        pd += __shfl_xor_sync(0xffffffffu, pd, 2);
        if ((lane & 3) == 0) {
            size_t o = ((size_t)bic * N_ + n) * H_ + h;
            *(float4*)(g_src4 + o * 4) = make_float4(ps, __expf(ps), __expf(0.2f * ps), 0.0f);
            *(float4*)(g_dst4 + o * 4) = make_float4(pd, __expf(pd), __expf(0.2f * pd), 0.0f);
        }
    }
}

// ============================================================================
// Kernel 2: attention, MUFU-free + 4-dst register blocking.
// grid: (4 dst-tiles of 128, 64 bic), block 256.
// Thread = (h = tid&7, dl = tid>>3); handles 4 consecutive dsts.
// exp(lrelu(ssrc+sdst)) = (t>=0) ? ep_s*ep_d : ep2_s*ep2_d  (pure FSEL/FMUL).
// Non-edges contribute exp(0)=1 (reference masks alpha to 0 pre-softmax).
// ============================================================================
#define TS 32
__global__ __launch_bounds__(256) void att_kernel(
    const int* __restrict__ A, const float* __restrict__ bias)
{
    const int bic  = blockIdx.y;
    const int tile = blockIdx.x;
    const int c    = bic & 1;
    const int bi   = bic >> 1;
    const int iord = bi & 1;
    const int tid  = threadIdx.x;
    const int h    = tid & 7;
    const int dl   = tid >> 3;             // 0..31
    const int dst0 = tile * 128 + dl * 4;  // 4 consecutive dsts

    __shared__ __align__(16) float sm_xh[TS][160];  // head-stride 20 -> conflict-free
    __shared__ __align__(16) float sm_ss[TS][32];   // [s][h*4] = {ss, p1, p2, -}
    __shared__ __align__(16) float sm_ae[TS][128];  // edge floats for 128 dsts

    const float* xp = g_xp + (size_t)bic * N_ * D_;
    const int*   Ab = A + (size_t)bi * N_ * N_ + tile * 128;
    const int    tgt = 2 + c;   // edge iff A==4 || A==tgt

    // per-dst destination-side values (raw score + exp forms)
    float sd[4], q1[4], q2[4], Z[4];
#pragma unroll
    for (int d = 0; d < 4; d++) {
        float4 v = *(const float4*)(g_dst4 + (((size_t)bic * N_ + dst0 + d) * H_ + h) * 4);
        sd[d] = v.x; q1[d] = v.y; q2[d] = v.z; Z[d] = 0.0f;
    }

    unsigned long long acc[4][8];
#pragma unroll
    for (int d = 0; d < 4; d++)
#pragma unroll
        for (int j = 0; j < 8; j++) acc[d][j] = 0ull;

    for (int s0 = 0; s0 < N_; s0 += TS) {
        __syncthreads();
        // xh tile: 32 x 128 floats -> head-stride-20 layout
#pragma unroll
        for (int k = 0; k < 4; k++) {
            int fid = tid + k * 256;
            int s = fid >> 5, dq = fid & 31;
            float4 v = *(const float4*)(xp + (size_t)(s0 + s) * D_ + dq * 4);
            *(float4*)&sm_xh[s][(dq >> 2) * 20 + (dq & 3) * 4] = v;
        }
        // src score tile: one float4 per (s,h)
        {
            int s = tid >> 3, hh = tid & 7;
            *(float4*)&sm_ss[s][hh * 4] =
                *(const float4*)(g_src4 + (((size_t)bic * N_ + s0 + s) * H_ + hh) * 4);
        }
        // A tile -> edge floats: 32 s x 128 dst
#pragma unroll
        for (int k = 0; k < 4; k++) {
            int fid = tid + k * 256;
            int s = fid >> 5, q = fid & 31;
            int4 avv = *(const int4*)(Ab + (size_t)(s0 + s) * N_ + q * 4);
            float4 ef;
            ef.x = (avv.x == 4 || avv.x == tgt) ? 1.0f : 0.0f;
            ef.y = (avv.y == 4 || avv.y == tgt) ? 1.0f : 0.0f;
            ef.z = (avv.z == 4 || avv.z == tgt) ? 1.0f : 0.0f;
            ef.w = (avv.w == 4 || avv.w == tgt) ? 1.0f : 0.0f;
            *(float4*)&sm_ae[s][q * 4] = ef;
        }
        __syncthreads();
#pragma unroll 4
        for (int s = 0; s < TS; s++) {
            float4 ssv = *(const float4*)&sm_ss[s][h * 4];   // {ss, p1, p2, -}
            float4 efv = *(const float4*)&sm_ae[s][dl * 4];  // edge flags, 4 dsts
            const float4* xr = (const float4*)&sm_xh[s][h * 20];
            float4 xa = xr[0], xb2 = xr[1], xc = xr[2], xd = xr[3];
            unsigned long long xv[8];
            xv[0] = pk2(xa.x, xa.y);  xv[1] = pk2(xa.z, xa.w);
            xv[2] = pk2(xb2.x, xb2.y); xv[3] = pk2(xb2.z, xb2.w);
            xv[4] = pk2(xc.x, xc.y);  xv[5] = pk2(xc.z, xc.w);
            xv[6] = pk2(xd.x, xd.y);  xv[7] = pk2(xd.z, xd.w);
            const float ef4[4] = {efv.x, efv.y, efv.z, efv.w};
#pragma unroll
            for (int d = 0; d < 4; d++) {
                float t  = ssv.x + sd[d];
                bool ge  = (t >= 0.0f);
                float pa = ge ? ssv.y : ssv.z;     // exp(ss) or exp(.2 ss)
                float qa = ge ? q1[d] : q2[d];     // exp(sd) or exp(.2 sd)
                float e  = pa * qa;                // exp(lrelu(ss+sd))
                float eb = fmaf(ef4[d], e - 1.0f, 1.0f);  // edge? e : 1
                Z[d] += eb;
                unsigned long long e2 = pk2(eb, eb);
#pragma unroll
                for (int j = 0; j < 8; j++) fma2(acc[d][j], e2, xv[j]);
            }
        }
    }

    // epilogue: /Z, + xp (add_self_loops), + bias
    float4 bq[4];
#pragma unroll
    for (int jj = 0; jj < 4; jj++)
        bq[jj] = *(const float4*)(bias + (iord * 2 + c) * D_ + h * DH_ + jj * 4);
#pragma unroll
    for (int d = 0; d < 4; d++) {
        const float invZ = 1.0f / Z[d];
        const float* xpd  = xp + (size_t)(dst0 + d) * D_ + h * DH_;
        float*       outp = g_att + (size_t)bic * N_ * D_ + (size_t)(dst0 + d) * D_ + h * DH_;
#pragma unroll
        for (int jj = 0; jj < 4; jj++) {
            float f0, f1, f2, f3;
            upk2(acc[d][2 * jj],     f0, f1);
            upk2(acc[d][2 * jj + 1], f2, f3);
            float4 xq = *(const float4*)(xpd + jj * 4);
            float4 o;
            o.x = f0 * invZ + xq.x + bq[jj].x;
            o.y = f1 * invZ + xq.y + bq[jj].y;
            o.z = f2 * invZ + xq.z + bq[jj].z;
            o.w = f3 * invZ + xq.w + bq[jj].w;
            *(float4*)(outp + jj * 4) = o;
        }
    }
}

// ============================================================================
// Kernel 3: combine.  h[b,i] = att[b,i,0] + att[b,i,1];
//           out[b,i] = h[b,i] + 0.5*(h[b,0] + h[b,1])
// ============================================================================
__global__ void combine_kernel(float4* __restrict__ out) {
    int gid = blockIdx.x * blockDim.x + threadIdx.x;   // 0 .. 16*16384-1
    int b = gid >> 14;
    int r = gid & 16383;
    const float4* a = (const float4*)g_att;
    float4 a00 = a[(size_t)(b * 4 + 0) * 16384 + r];
    float4 a01 = a[(size_t)(b * 4 + 1) * 16384 + r];
    float4 a10 = a[(size_t)(b * 4 + 2) * 16384 + r];
    float4 a11 = a[(size_t)(b * 4 + 3) * 16384 + r];
    float4 h0, h1, o0, o1;
    h0.x = a00.x + a01.x; h0.y = a00.y + a01.y; h0.z = a00.z + a01.z; h0.w = a00.w + a01.w;
    h1.x = a10.x + a11.x; h1.y = a10.y + a11.y; h1.z = a10.z + a11.z; h1.w = a10.w + a11.w;
    float mx = 0.5f * (h0.x + h1.x), my = 0.5f * (h0.y + h1.y);
    float mz = 0.5f * (h0.z + h1.z), mw = 0.5f * (h0.w + h1.w);
    o0.x = h0.x + mx; o0.y = h0.y + my; o0.z = h0.z + mz; o0.w = h0.w + mw;
    o1.x = h1.x + mx; o1.y = h1.y + my; o1.z = h1.z + mz; o1.w = h1.w + mw;
    out[(size_t)(b * 2 + 0) * 16384 + r] = o0;
    out[(size_t)(b * 2 + 1) * 16384 + r] = o1;
}

// ============================================================================
extern "C" void kernel_launch(void* const* d_in, const int* in_sizes, int n_in,
                              void* d_out, int out_size) {
    const float* x    = (const float*)d_in[0];
    const int*   A    = (const int*)  d_in[1];
    const float* W    = (const float*)d_in[2];
    const float* pb   = (const float*)d_in[3];
    const float* asrc = (const float*)d_in[4];
    const float* adst = (const float*)d_in[5];
    const float* bias = (const float*)d_in[6];

    proj_kernel<<<dim3(8, 64), 256>>>(x, W, pb, asrc, adst);
    att_kernel<<<dim3(4, 64), 256>>>(A, bias);
    combine_kernel<<<1024, 256>>>((float4*)d_out);
}

// round 8
// speedup vs baseline: 1.6132x; 1.0216x over previous
#include <cuda_runtime.h>

#define B_ 16
#define ORDER_ 2
#define N_ 512
#define D_ 128
#define H_ 8
#define DH_ 16
#define NBIC 64   // B*ORDER*2 (b,i,c) combos

// ---------------- scratch (device globals; no allocations) ----------------
__device__ __align__(16) float g_xp  [NBIC * N_ * D_];       // projected features (+pb)
__device__ __align__(16) float g_src4[NBIC * N_ * H_ * 4];   // {ssrc, exp(ssrc), exp(.2 ssrc), 0}
__device__ __align__(16) float g_dst4[NBIC * N_ * H_ * 4];   // {sdst, exp(sdst), exp(.2 sdst), 0}
__device__ __align__(16) float g_ae  [(size_t)NBIC * N_ * N_]; // edge masks as float (per bic)
__device__ __align__(16) float g_att [NBIC * N_ * D_];       // per-conv GAT output (+xp +bias)

// ---------------- packed f32x2 helpers ----------------
__device__ __forceinline__ unsigned long long pk2(float a, float b) {
    unsigned long long r;
    asm("mov.b64 %0, {%1, %2};" : "=l"(r) : "r"(__float_as_uint(a)), "r"(__float_as_uint(b)));
    return r;
}
__device__ __forceinline__ void upk2(unsigned long long v, float& a, float& b) {
    unsigned int lo, hi;
    asm("mov.b64 {%0, %1}, %2;" : "=r"(lo), "=r"(hi) : "l"(v));
    a = __uint_as_float(lo); b = __uint_as_float(hi);
}
__device__ __forceinline__ void fma2(unsigned long long& d, unsigned long long a, unsigned long long b) {
    asm("fma.rn.f32x2 %0, %1, %2, %0;" : "+l"(d) : "l"(a), "l"(b));
}
__device__ __forceinline__ void cpa16(unsigned int s, const void* g) {
    asm volatile("cp.async.cg.shared.global [%0], [%1], 16;" :: "r"(s), "l"(g) : "memory");
}
__device__ __forceinline__ void cpa_commit() {
    asm volatile("cp.async.commit_group;" ::: "memory");
}
__device__ __forceinline__ void cpa_wait0() {
    asm volatile("cp.async.wait_group 0;" ::: "memory");
}

// ============================================================================
// Kernel 0: edge masks.  g_ae[bi*2+c][s][d] = (A==4 || A==2+c) ? 1 : 0
// ============================================================================
__global__ __launch_bounds__(256) void mask_kernel(const int4* __restrict__ A4) {
    int gid = blockIdx.x * 256 + threadIdx.x;   // 0 .. 32*512*512/4 - 1
    int4 a = A4[gid];
    float4 m0, m1;
    m0.x = (a.x == 4 || a.x == 2) ? 1.0f : 0.0f;
    m0.y = (a.y == 4 || a.y == 2) ? 1.0f : 0.0f;
    m0.z = (a.z == 4 || a.z == 2) ? 1.0f : 0.0f;
    m0.w = (a.w == 4 || a.w == 2) ? 1.0f : 0.0f;
    m1.x = (a.x == 4 || a.x == 3) ? 1.0f : 0.0f;
    m1.y = (a.y == 4 || a.y == 3) ? 1.0f : 0.0f;
    m1.z = (a.z == 4 || a.z == 3) ? 1.0f : 0.0f;
    m1.w = (a.w == 4 || a.w == 3) ? 1.0f : 0.0f;
    int bi = gid >> 16;              // 65536 float4-chunks per bi (512*512/4)
    int r  = gid & 65535;
    float4* ae4 = (float4*)g_ae;
    ae4[(size_t)(bi * 2 + 0) * 65536 + r] = m0;
    ae4[(size_t)(bi * 2 + 1) * 65536 + r] = m1;
}

// ============================================================================
// Kernel 1: projection xp = x @ W^T + pb  (per (b,i,c)),
//           fused epilogue computes ssrc/sdst head dots AND their exp forms.
// grid: (8 n-tiles, 64 bic), block 256.
// ============================================================================
__global__ __launch_bounds__(256) void proj_kernel(
    const float* __restrict__ x, const float* __restrict__ W, const float* __restrict__ pb,
    const float* __restrict__ asrc, const float* __restrict__ adst)
{
    const int bic  = blockIdx.y;
    const int nt   = blockIdx.x;
    const int c    = bic & 1;
    const int bi   = bic >> 1;
    const int iord = bi & 1;
    const int tid  = threadIdx.x;
    const int lane = tid & 31, warp = tid >> 5;

    __shared__ __align__(16) float xs[64][36];    // [n][k] (pad 4)
    __shared__ __align__(16) float wt[32][128];   // [k][d], XOR-swizzled float4 columns

    const float* xb = x + ((size_t)bi * N_ + nt * 64) * D_;
    const float* Wb = W + (size_t)(iord * 2 + c) * D_ * D_;

    unsigned long long acc[8][2];
#pragma unroll
    for (int r = 0; r < 8; r++) { acc[r][0] = 0ull; acc[r][1] = 0ull; }

    for (int kc = 0; kc < 4; kc++) {
        __syncthreads();
#pragma unroll
        for (int t2 = 0; t2 < 2; t2++) {
            int fid = tid + t2 * 256;
            int s = fid >> 3, kq = fid & 7;
            float4 v = *(const float4*)(xb + (size_t)s * D_ + kc * 32 + kq * 4);
            *(float4*)&xs[s][kq * 4] = v;
        }
#pragma unroll
        for (int t4 = 0; t4 < 4; t4++) {
            int fid = tid + t4 * 256;
            int d = fid >> 3, kq = fid & 7;
            float4 v = *(const float4*)(Wb + (size_t)d * D_ + kc * 32 + kq * 4);
            int d4 = d >> 2, dr = d & 3;
            wt[kq * 4 + 0][((d4 ^ (kq * 4 + 0)) << 2) + dr] = v.x;
            wt[kq * 4 + 1][((d4 ^ (kq * 4 + 1)) << 2) + dr] = v.y;
            wt[kq * 4 + 2][((d4 ^ (kq * 4 + 2)) << 2) + dr] = v.z;
            wt[kq * 4 + 3][((d4 ^ (kq * 4 + 3)) << 2) + dr] = v.w;
        }
        __syncthreads();
#pragma unroll 4
        for (int k = 0; k < 32; k++) {
            float4 wv = *(const float4*)&wt[k][(lane ^ k) << 2];
            unsigned long long w01 = pk2(wv.x, wv.y);
            unsigned long long w23 = pk2(wv.z, wv.w);
#pragma unroll
            for (int r = 0; r < 8; r++) {
                float a = xs[warp * 8 + r][k];
                unsigned long long a2 = pk2(a, a);
                fma2(acc[r][0], a2, w01);
                fma2(acc[r][1], a2, w23);
            }
        }
    }

    const float4 pbv = *(const float4*)(pb + (iord * 2 + c) * D_ + lane * 4);
    const int h  = lane >> 2;
    const int fb = (lane & 3) * 4;
    const float4 av = *(const float4*)(asrc + ((iord * 2 + c) * H_ + h) * DH_ + fb);
    const float4 dv = *(const float4*)(adst + ((iord * 2 + c) * H_ + h) * DH_ + fb);
#pragma unroll
    for (int r = 0; r < 8; r++) {
        int n = nt * 64 + warp * 8 + r;
        float x0, x1, x2, x3;
        upk2(acc[r][0], x0, x1);
        upk2(acc[r][1], x2, x3);
        x0 += pbv.x; x1 += pbv.y; x2 += pbv.z; x3 += pbv.w;
        *(float4*)(g_xp + ((size_t)bic * N_ + n) * D_ + lane * 4) = make_float4(x0, x1, x2, x3);
        float ps = x0 * av.x + x1 * av.y + x2 * av.z + x3 * av.w;
        float pd = x0 * dv.x + x1 * dv.y + x2 * dv.z + x3 * dv.w;
        ps += __shfl_xor_sync(0xffffffffu, ps, 1);
        ps += __shfl_xor_sync(0xffffffffu, ps, 2);
        pd += __shfl_xor_sync(0xffffffffu, pd, 1);
        pd += __shfl_xor_sync(0xffffffffu, pd, 2);
        if ((lane & 3) == 0) {
            size_t o = ((size_t)bic * N_ + n) * H_ + h;
            *(float4*)(g_src4 + o * 4) = make_float4(ps, __expf(ps), __expf(0.2f * ps), 0.0f);
            *(float4*)(g_dst4 + o * 4) = make_float4(pd, __expf(pd), __expf(0.2f * pd), 0.0f);
        }
    }
}

// ============================================================================
// Kernel 2: attention, cp.async double-buffered, MUFU-free, 4-dst blocking.
// grid: (4 dst-tiles of 128, 64 bic), block 256, dyn smem 80 KB (2 blocks/SM).
// Per-buffer float layout: [0,5120) xh(32x160, head-stride 20)
//                          [5120,6144) ss(32x32)   [6144,10240) ae(32x128)
// ============================================================================
#define TS 32
#define BUF_FLOATS 10240

__global__ __launch_bounds__(256, 2) void att_kernel(const float* __restrict__ bias)
{
    extern __shared__ __align__(16) float smem[];
    const int bic  = blockIdx.y;
    const int tile = blockIdx.x;
    const int c    = bic & 1;
    const int bi   = bic >> 1;
    const int iord = bi & 1;
    const int tid  = threadIdx.x;
    const int h    = tid & 7;
    const int dl   = tid >> 3;             // 0..31
    const int dst0 = tile * 128 + dl * 4;  // 4 consecutive dsts

    unsigned int sbase;
    asm("{.reg .u64 t; cvta.to.shared.u64 t, %1; cvt.u32.u64 %0, t;}"
        : "=r"(sbase) : "l"(smem));

    const float* xp    = g_xp   + (size_t)bic * N_ * D_;
    const float* src4p = g_src4 + (size_t)bic * N_ * H_ * 4;
    const float* aegp  = g_ae   + ((size_t)bic * N_) * N_ + tile * 128;

    // fill indices (fixed per thread)
    const int xs_s = tid >> 5, xs_dq = tid & 31;            // +k*8 rows
    const int ss_s = tid >> 3, ss_h = tid & 7;

    // per-dst destination-side values
    float sd[4], q1[4], q2[4], Z[4];
#pragma unroll
    for (int d = 0; d < 4; d++) {
        float4 v = *(const float4*)(g_dst4 + (((size_t)bic * N_ + dst0 + d) * H_ + h) * 4);
        sd[d] = v.x; q1[d] = v.y; q2[d] = v.z; Z[d] = 0.0f;
    }

    unsigned long long acc[4][8];
#pragma unroll
    for (int d = 0; d < 4; d++)
#pragma unroll
        for (int j = 0; j < 8; j++) acc[d][j] = 0ull;

    // ---- issue helper (tile t into buffer buf) ----
    auto issue = [&](int t, int buf) {
        const int s0 = t * TS;
        const unsigned int b = sbase + buf * (BUF_FLOATS * 4);
#pragma unroll
        for (int k = 0; k < 4; k++) {
            int s = xs_s + k * 8;
            cpa16(b + (unsigned)(s * 640 + (xs_dq >> 2) * 80 + (xs_dq & 3) * 16),
                  xp + (size_t)(s0 + s) * D_ + xs_dq * 4);
        }
        cpa16(b + 20480u + (unsigned)(ss_s * 128 + ss_h * 16),
              src4p + ((size_t)(s0 + ss_s) * H_ + ss_h) * 4);
#pragma unroll
        for (int k = 0; k < 4; k++) {
            int s = xs_s + k * 8;
            cpa16(b + 24576u + (unsigned)(s * 512 + xs_dq * 16),
                  aegp + (size_t)(s0 + s) * N_ + xs_dq * 4);
        }
        cpa_commit();
    };

    issue(0, 0);

#pragma unroll 1
    for (int t = 0; t < N_ / TS; t++) {
        const int p = t & 1;
        cpa_wait0();          // tile t's copies (issued by this thread) complete
        __syncthreads();      // visible to all; everyone done with buf 1-p
        if (t < N_ / TS - 1) issue(t + 1, 1 - p);

        const float* xhp = smem + p * BUF_FLOATS;
        const float* ssp = xhp + 5120;
        const float* aep = xhp + 6144;
#pragma unroll 4
        for (int s = 0; s < TS; s++) {
            float4 ssv = *(const float4*)(ssp + s * 32 + h * 4);   // {ss, p1, p2, -}
            float4 efv = *(const float4*)(aep + s * 128 + dl * 4); // edge flags
            const ulonglong2* xr = (const ulonglong2*)(xhp + s * 160 + h * 20);
            ulonglong2 xA = xr[0], xB = xr[1];
            unsigned long long xv0 = xA.x, xv1 = xA.y, xv2 = xB.x, xv3 = xB.y;
            const float ef4[4] = {efv.x, efv.y, efv.z, efv.w};
#pragma unroll
            for (int d = 0; d < 4; d++) {
                float t0 = ssv.x + sd[d];
                bool ge  = (t0 >= 0.0f);
                float pa = ge ? ssv.y : ssv.z;
                float qa = ge ? q1[d] : q2[d];
                float e  = pa * qa;                        // exp(lrelu(ss+sd))
                float eb = fmaf(ef4[d], e - 1.0f, 1.0f);   // edge? e : 1
                Z[d] += eb;
                unsigned long long e2 = pk2(eb, eb);
                fma2(acc[d][0], e2, xv0);
                fma2(acc[d][1], e2, xv1);
                fma2(acc[d][2], e2, xv2);
                fma2(acc[d][3], e2, xv3);
            }
            const ulonglong2* xr2 = xr + 2;
            ulonglong2 xC = xr2[0], xD = xr2[1];
            unsigned long long xv4 = xC.x, xv5 = xC.y, xv6 = xD.x, xv7 = xD.y;
#pragma unroll
            for (int d = 0; d < 4; d++) {
                float t0 = ssv.x + sd[d];
                bool ge  = (t0 >= 0.0f);
                float pa = ge ? ssv.y : ssv.z;
                float qa = ge ? q1[d] : q2[d];
                float eb = fmaf(ef4[d], pa * qa - 1.0f, 1.0f);
                unsigned long long e2 = pk2(eb, eb);
                fma2(acc[d][4], e2, xv4);
                fma2(acc[d][5], e2, xv5);
                fma2(acc[d][6], e2, xv6);
                fma2(acc[d][7], e2, xv7);
            }
        }
    }

    // epilogue: /Z, + xp (add_self_loops), + bias
    float4 bq[4];
#pragma unroll
    for (int jj = 0; jj < 4; jj++)
        bq[jj] = *(const float4*)(bias + (iord * 2 + c) * D_ + h * DH_ + jj * 4);
#pragma unroll
    for (int d = 0; d < 4; d++) {
        const float invZ = 1.0f / Z[d];
        const float* xpd  = xp + (size_t)(dst0 + d) * D_ + h * DH_;
        float*       outp = g_att + (size_t)bic * N_ * D_ + (size_t)(dst0 + d) * D_ + h * DH_;
#pragma unroll
        for (int jj = 0; jj < 4; jj++) {
            float f0, f1, f2, f3;
            upk2(acc[d][2 * jj],     f0, f1);
            upk2(acc[d][2 * jj + 1], f2, f3);
            float4 xq = *(const float4*)(xpd + jj * 4);
            float4 o;
            o.x = f0 * invZ + xq.x + bq[jj].x;
            o.y = f1 * invZ + xq.y + bq[jj].y;
            o.z = f2 * invZ + xq.z + bq[jj].z;
            o.w = f3 * invZ + xq.w + bq[jj].w;
            *(float4*)(outp + jj * 4) = o;
        }
    }
}

// ============================================================================
// Kernel 3: combine.  h[b,i] = att[b,i,0] + att[b,i,1];
//           out[b,i] = h[b,i] + 0.5*(h[b,0] + h[b,1])
// ============================================================================
__global__ void combine_kernel(float4* __restrict__ out) {
    int gid = blockIdx.x * blockDim.x + threadIdx.x;   // 0 .. 16*16384-1
    int b = gid >> 14;
    int r = gid & 16383;
    const float4* a = (const float4*)g_att;
    float4 a00 = a[(size_t)(b * 4 + 0) * 16384 + r];
    float4 a01 = a[(size_t)(b * 4 + 1) * 16384 + r];
    float4 a10 = a[(size_t)(b * 4 + 2) * 16384 + r];
    float4 a11 = a[(size_t)(b * 4 + 3) * 16384 + r];
    float4 h0, h1, o0, o1;
    h0.x = a00.x + a01.x; h0.y = a00.y + a01.y; h0.z = a00.z + a01.z; h0.w = a00.w + a01.w;
    h1.x = a10.x + a11.x; h1.y = a10.y + a11.y; h1.z = a10.z + a11.z; h1.w = a10.w + a11.w;
    float mx = 0.5f * (h0.x + h1.x), my = 0.5f * (h0.y + h1.y);
    float mz = 0.5f * (h0.z + h1.z), mw = 0.5f * (h0.w + h1.w);
    o0.x = h0.x + mx; o0.y = h0.y + my; o0.z = h0.z + mz; o0.w = h0.w + mw;
    o1.x = h1.x + mx; o1.y = h1.y + my; o1.z = h1.z + mz; o1.w = h1.w + mw;
    out[(size_t)(b * 2 + 0) * 16384 + r] = o0;
    out[(size_t)(b * 2 + 1) * 16384 + r] = o1;
}

// ============================================================================
extern "C" void kernel_launch(void* const* d_in, const int* in_sizes, int n_in,
                              void* d_out, int out_size) {
    const float* x    = (const float*)d_in[0];
    const int*   A    = (const int*)  d_in[1];
    const float* W    = (const float*)d_in[2];
    const float* pb   = (const float*)d_in[3];
    const float* asrc = (const float*)d_in[4];
    const float* adst = (const float*)d_in[5];
    const float* bias = (const float*)d_in[6];

    cudaFuncSetAttribute(att_kernel, cudaFuncAttributeMaxDynamicSharedMemorySize,
                         2 * BUF_FLOATS * 4);

    mask_kernel<<<8192, 256>>>((const int4*)A);
    proj_kernel<<<dim3(8, 64), 256>>>(x, W, pb, asrc, adst);
    att_kernel<<<dim3(4, 64), 256, 2 * BUF_FLOATS * 4>>>(bias);
    combine_kernel<<<1024, 256>>>((float4*)d_out);
}

// round 9
// speedup vs baseline: 1.6981x; 1.0527x over previous
#include <cuda_runtime.h>

#define B_ 16
#define ORDER_ 2
#define N_ 512
#define D_ 128
#define H_ 8
#define DH_ 16
#define NBIC 64   // B*ORDER*2 (b,i,c) combos

// ---------------- scratch (device globals; no allocations) ----------------
__device__ __align__(16) float g_xp  [NBIC * N_ * D_];       // projected features (+pb)
__device__ __align__(16) float g_src4[NBIC * N_ * H_ * 4];   // {ssrc, exp(ssrc), exp(.2 ssrc), 0}
__device__ __align__(16) float g_dst4[NBIC * N_ * H_ * 4];   // {sdst, exp(sdst), exp(.2 sdst), 0}
__device__ __align__(16) unsigned int g_mask[NBIC * N_ * (N_ / 32)]; // 1 bit per edge (2 MB)
__device__ __align__(16) float g_att [NBIC * N_ * D_];       // per-conv GAT output (+xp +bias)

// ---------------- packed f32x2 helpers ----------------
__device__ __forceinline__ unsigned long long pk2(float a, float b) {
    unsigned long long r;
    asm("mov.b64 %0, {%1, %2};" : "=l"(r) : "r"(__float_as_uint(a)), "r"(__float_as_uint(b)));
    return r;
}
__device__ __forceinline__ void upk2(unsigned long long v, float& a, float& b) {
    unsigned int lo, hi;
    asm("mov.b64 {%0, %1}, %2;" : "=r"(lo), "=r"(hi) : "l"(v));
    a = __uint_as_float(lo); b = __uint_as_float(hi);
}
__device__ __forceinline__ void fma2(unsigned long long& d, unsigned long long a, unsigned long long b) {
    asm("fma.rn.f32x2 %0, %1, %2, %0;" : "+l"(d) : "l"(a), "l"(b));
}
__device__ __forceinline__ void cpa16(unsigned int s, const void* g) {
    asm volatile("cp.async.cg.shared.global [%0], [%1], 16;" :: "r"(s), "l"(g) : "memory");
}
__device__ __forceinline__ void cpa_commit() {
    asm volatile("cp.async.commit_group;" ::: "memory");
}
__device__ __forceinline__ void cpa_wait0() {
    asm volatile("cp.async.wait_group 0;" ::: "memory");
}

// ============================================================================
// Kernel 0: bit-packed edge masks via ballot.
// warp = (bi, s, w); lane = dst w*32+lane.  m0: c=0 (A==2|4), m1: c=1 (A==3|4)
// g_mask[((bi*2+c)*512 + s)*16 + w], bit j = edge(s, w*32+j)
// ============================================================================
__global__ __launch_bounds__(256) void mask_kernel(const int* __restrict__ A) {
    int gid  = blockIdx.x * 256 + threadIdx.x;
    int lane = gid & 31;
    int wlin = gid >> 5;            // 0 .. 32*512*16-1
    int bi   = wlin >> 13;          // 8192 warps per bi
    int rr   = wlin & 8191;
    int s    = rr >> 4, w = rr & 15;
    int a = A[((size_t)(bi * N_ + s)) * N_ + w * 32 + lane];
    unsigned int m0 = __ballot_sync(0xffffffffu, a == 4 || a == 2);
    unsigned int m1 = __ballot_sync(0xffffffffu, a == 4 || a == 3);
    if (lane == 0) g_mask[((size_t)(bi * 2 + 0) * N_ + s) * 16 + w] = m0;
    if (lane == 1) g_mask[((size_t)(bi * 2 + 1) * N_ + s) * 16 + w] = m1;
}

// ============================================================================
// Kernel 1: projection xp = x @ W^T + pb  (per (b,i,c)),
//           fused epilogue computes ssrc/sdst head dots AND their exp forms.
// grid: (8 n-tiles, 64 bic), block 256.
// ============================================================================
__global__ __launch_bounds__(256) void proj_kernel(
    const float* __restrict__ x, const float* __restrict__ W, const float* __restrict__ pb,
    const float* __restrict__ asrc, const float* __restrict__ adst)
{
    const int bic  = blockIdx.y;
    const int nt   = blockIdx.x;
    const int c    = bic & 1;
    const int bi   = bic >> 1;
    const int iord = bi & 1;
    const int tid  = threadIdx.x;
    const int lane = tid & 31, warp = tid >> 5;

    __shared__ __align__(16) float xs[64][36];    // [n][k] (pad 4)
    __shared__ __align__(16) float wt[32][128];   // [k][d], XOR-swizzled float4 columns

    const float* xb = x + ((size_t)bi * N_ + nt * 64) * D_;
    const float* Wb = W + (size_t)(iord * 2 + c) * D_ * D_;

    unsigned long long acc[8][2];
#pragma unroll
    for (int r = 0; r < 8; r++) { acc[r][0] = 0ull; acc[r][1] = 0ull; }

    for (int kc = 0; kc < 4; kc++) {
        __syncthreads();
#pragma unroll
        for (int t2 = 0; t2 < 2; t2++) {
            int fid = tid + t2 * 256;
            int s = fid >> 3, kq = fid & 7;
            float4 v = *(const float4*)(xb + (size_t)s * D_ + kc * 32 + kq * 4);
            *(float4*)&xs[s][kq * 4] = v;
        }
#pragma unroll
        for (int t4 = 0; t4 < 4; t4++) {
            int fid = tid + t4 * 256;
            int d = fid >> 3, kq = fid & 7;
            float4 v = *(const float4*)(Wb + (size_t)d * D_ + kc * 32 + kq * 4);
            int d4 = d >> 2, dr = d & 3;
            wt[kq * 4 + 0][((d4 ^ (kq * 4 + 0)) << 2) + dr] = v.x;
            wt[kq * 4 + 1][((d4 ^ (kq * 4 + 1)) << 2) + dr] = v.y;
            wt[kq * 4 + 2][((d4 ^ (kq * 4 + 2)) << 2) + dr] = v.z;
            wt[kq * 4 + 3][((d4 ^ (kq * 4 + 3)) << 2) + dr] = v.w;
        }
        __syncthreads();
#pragma unroll 4
        for (int k = 0; k < 32; k++) {
            float4 wv = *(const float4*)&wt[k][(lane ^ k) << 2];
            unsigned long long w01 = pk2(wv.x, wv.y);
            unsigned long long w23 = pk2(wv.z, wv.w);
#pragma unroll
            for (int r = 0; r < 8; r++) {
                float a = xs[warp * 8 + r][k];
                unsigned long long a2 = pk2(a, a);
                fma2(acc[r][0], a2, w01);
                fma2(acc[r][1], a2, w23);
            }
        }
    }

    const float4 pbv = *(const float4*)(pb + (iord * 2 + c) * D_ + lane * 4);
    const int h  = lane >> 2;
    const int fb = (lane & 3) * 4;
    const float4 av = *(const float4*)(asrc + ((iord * 2 + c) * H_ + h) * DH_ + fb);
    const float4 dv = *(const float4*)(adst + ((iord * 2 + c) * H_ + h) * DH_ + fb);
#pragma unroll
    for (int r = 0; r < 8; r++) {
        int n = nt * 64 + warp * 8 + r;
        float x0, x1, x2, x3;
        upk2(acc[r][0], x0, x1);
        upk2(acc[r][1], x2, x3);
        x0 += pbv.x; x1 += pbv.y; x2 += pbv.z; x3 += pbv.w;
        *(float4*)(g_xp + ((size_t)bic * N_ + n) * D_ + lane * 4) = make_float4(x0, x1, x2, x3);
        float ps = x0 * av.x + x1 * av.y + x2 * av.z + x3 * av.w;
        float pd = x0 * dv.x + x1 * dv.y + x2 * dv.z + x3 * dv.w;
        ps += __shfl_xor_sync(0xffffffffu, ps, 1);
        ps += __shfl_xor_sync(0xffffffffu, ps, 2);
        pd += __shfl_xor_sync(0xffffffffu, pd, 1);
        pd += __shfl_xor_sync(0xffffffffu, pd, 2);
        if ((lane & 3) == 0) {
            size_t o = ((size_t)bic * N_ + n) * H_ + h;
            *(float4*)(g_src4 + o * 4) = make_float4(ps, __expf(ps), __expf(0.2f * ps), 0.0f);
            *(float4*)(g_dst4 + o * 4) = make_float4(pd, __expf(pd), __expf(0.2f * pd), 0.0f);
        }
    }
}

// ============================================================================
// Kernel 2: attention, cp.async double-buffered, MUFU-free, 4-dst blocking,
//           bit-packed edge masks, deduped score computation.
// grid: (4 dst-tiles of 128, 64 bic), block 256.
// Per-buffer float layout: [0,5120) xh(32x160, head-stride 20)
//                          [5120,6144) ss(32x32)  [6144,6272) mask (32 s x 4 u32)
// ============================================================================
#define TS 32
#define BUF_FLOATS 6272

__global__ __launch_bounds__(256, 2) void att_kernel(const float* __restrict__ bias)
{
    extern __shared__ __align__(16) float smem[];
    const int bic  = blockIdx.y;
    const int tile = blockIdx.x;
    const int c    = bic & 1;
    const int bi   = bic >> 1;
    const int iord = bi & 1;
    const int tid  = threadIdx.x;
    const int h    = tid & 7;
    const int dl   = tid >> 3;             // 0..31
    const int dst0 = tile * 128 + dl * 4;  // 4 consecutive dsts
    const int wsel = dl >> 3;              // mask word within the 4 covering this tile
    const int shft = (dl & 7) * 4;         // bit offset of this thread's 4 dsts

    unsigned int sbase;
    asm("{.reg .u64 t; cvta.to.shared.u64 t, %1; cvt.u32.u64 %0, t;}"
        : "=r"(sbase) : "l"(smem));

    const float* xp    = g_xp   + (size_t)bic * N_ * D_;
    const float* src4p = g_src4 + (size_t)bic * N_ * H_ * 4;
    const unsigned int* mgp = g_mask + (size_t)bic * N_ * 16 + tile * 4;

    const int xs_s = tid >> 5, xs_dq = tid & 31;  // +k*8 rows
    const int ss_s = tid >> 3, ss_h = tid & 7;

    float sd[4], q1[4], q2[4], Z[4];
#pragma unroll
    for (int d = 0; d < 4; d++) {
        float4 v = *(const float4*)(g_dst4 + (((size_t)bic * N_ + dst0 + d) * H_ + h) * 4);
        sd[d] = v.x; q1[d] = v.y; q2[d] = v.z; Z[d] = 0.0f;
    }

    unsigned long long acc[4][8];
#pragma unroll
    for (int d = 0; d < 4; d++)
#pragma unroll
        for (int j = 0; j < 8; j++) acc[d][j] = 0ull;

    auto issue = [&](int t, int buf) {
        const int s0 = t * TS;
        const unsigned int b = sbase + buf * (BUF_FLOATS * 4);
#pragma unroll
        for (int k = 0; k < 4; k++) {
            int s = xs_s + k * 8;
            cpa16(b + (unsigned)(s * 640 + (xs_dq >> 2) * 80 + (xs_dq & 3) * 16),
                  xp + (size_t)(s0 + s) * D_ + xs_dq * 4);
        }
        cpa16(b + 20480u + (unsigned)(ss_s * 128 + ss_h * 16),
              src4p + ((size_t)(s0 + ss_s) * H_ + ss_h) * 4);
        if (tid < 32)
            cpa16(b + 24576u + (unsigned)(tid * 16), mgp + (size_t)(s0 + tid) * 16);
        cpa_commit();
    };

    issue(0, 0);

#pragma unroll 1
    for (int t = 0; t < N_ / TS; t++) {
        const int p = t & 1;
        cpa_wait0();
        __syncthreads();
        if (t < N_ / TS - 1) issue(t + 1, 1 - p);

        const float* xhp = smem + p * BUF_FLOATS;
        const float* ssp = xhp + 5120;
        const unsigned int* mkp = (const unsigned int*)(xhp + 6144);
#pragma unroll 4
        for (int s = 0; s < TS; s++) {
            float4 ssv = *(const float4*)(ssp + s * 32 + h * 4);     // {ss, p1, p2, -}
            unsigned int bits = mkp[s * 4 + wsel] >> shft;           // 4 edge bits
            const ulonglong2* xr = (const ulonglong2*)(xhp + s * 160 + h * 20);
            ulonglong2 xA = xr[0], xB = xr[1], xC = xr[2], xD = xr[3];

            float eb4[4];
#pragma unroll
            for (int d = 0; d < 4; d++) {
                float t0 = ssv.x + sd[d];
                bool ge  = (t0 >= 0.0f);
                float pa = ge ? ssv.y : ssv.z;       // exp(ss) or exp(.2 ss)
                float qa = ge ? q1[d] : q2[d];       // exp(sd) or exp(.2 sd)
                float e  = pa * qa;                  // exp(lrelu(ss+sd))
                float eb = (bits & (1u << d)) ? e : 1.0f;  // edge? e : 1
                Z[d] += eb;
                eb4[d] = eb;
            }
#pragma unroll
            for (int d = 0; d < 4; d++) {
                unsigned long long e2 = pk2(eb4[d], eb4[d]);
                fma2(acc[d][0], e2, xA.x);
                fma2(acc[d][1], e2, xA.y);
                fma2(acc[d][2], e2, xB.x);
                fma2(acc[d][3], e2, xB.y);
                fma2(acc[d][4], e2, xC.x);
                fma2(acc[d][5], e2, xC.y);
                fma2(acc[d][6], e2, xD.x);
                fma2(acc[d][7], e2, xD.y);
            }
        }
    }

    // epilogue: /Z, + xp (add_self_loops), + bias
    float4 bq[4];
#pragma unroll
    for (int jj = 0; jj < 4; jj++)
        bq[jj] = *(const float4*)(bias + (iord * 2 + c) * D_ + h * DH_ + jj * 4);
#pragma unroll
    for (int d = 0; d < 4; d++) {
        const float invZ = 1.0f / Z[d];
        const float* xpd  = xp + (size_t)(dst0 + d) * D_ + h * DH_;
        float*       outp = g_att + (size_t)bic * N_ * D_ + (size_t)(dst0 + d) * D_ + h * DH_;
#pragma unroll
        for (int jj = 0; jj < 4; jj++) {
            float f0, f1, f2, f3;
            upk2(acc[d][2 * jj],     f0, f1);
            upk2(acc[d][2 * jj + 1], f2, f3);
            float4 xq = *(const float4*)(xpd + jj * 4);
            float4 o;
            o.x = f0 * invZ + xq.x + bq[jj].x;
            o.y = f1 * invZ + xq.y + bq[jj].y;
            o.z = f2 * invZ + xq.z + bq[jj].z;
            o.w = f3 * invZ + xq.w + bq[jj].w;
            *(float4*)(outp + jj * 4) = o;
        }
    }
}

// ============================================================================
// Kernel 3: combine.  h[b,i] = att[b,i,0] + att[b,i,1];
//           out[b,i] = h[b,i] + 0.5*(h[b,0] + h[b,1])
// ============================================================================
__global__ void combine_kernel(float4* __restrict__ out) {
    int gid = blockIdx.x * blockDim.x + threadIdx.x;   // 0 .. 16*16384-1
    int b = gid >> 14;
    int r = gid & 16383;
    const float4* a = (const float4*)g_att;
    float4 a00 = a[(size_t)(b * 4 + 0) * 16384 + r];
    float4 a01 = a[(size_t)(b * 4 + 1) * 16384 + r];
    float4 a10 = a[(size_t)(b * 4 + 2) * 16384 + r];
    float4 a11 = a[(size_t)(b * 4 + 3) * 16384 + r];
    float4 h0, h1, o0, o1;
    h0.x = a00.x + a01.x; h0.y = a00.y + a01.y; h0.z = a00.z + a01.z; h0.w = a00.w + a01.w;
    h1.x = a10.x + a11.x; h1.y = a10.y + a11.y; h1.z = a10.z + a11.z; h1.w = a10.w + a11.w;
    float mx = 0.5f * (h0.x + h1.x), my = 0.5f * (h0.y + h1.y);
    float mz = 0.5f * (h0.z + h1.z), mw = 0.5f * (h0.w + h1.w);
    o0.x = h0.x + mx; o0.y = h0.y + my; o0.z = h0.z + mz; o0.w = h0.w + mw;
    o1.x = h1.x + mx; o1.y = h1.y + my; o1.z = h1.z + mz; o1.w = h1.w + mw;
    out[(size_t)(b * 2 + 0) * 16384 + r] = o0;
    out[(size_t)(b * 2 + 1) * 16384 + r] = o1;
}

// ============================================================================
extern "C" void kernel_launch(void* const* d_in, const int* in_sizes, int n_in,
                              void* d_out, int out_size) {
    const float* x    = (const float*)d_in[0];
    const int*   A    = (const int*)  d_in[1];
    const float* W    = (const float*)d_in[2];
    const float* pb   = (const float*)d_in[3];
    const float* asrc = (const float*)d_in[4];
    const float* adst = (const float*)d_in[5];
    const float* bias = (const float*)d_in[6];

    cudaFuncSetAttribute(att_kernel, cudaFuncAttributeMaxDynamicSharedMemorySize,
                         2 * BUF_FLOATS * 4);

    mask_kernel<<<32768, 256>>>(A);
    proj_kernel<<<dim3(8, 64), 256>>>(x, W, pb, asrc, adst);
    att_kernel<<<dim3(4, 64), 256, 2 * BUF_FLOATS * 4>>>(bias);
    combine_kernel<<<1024, 256>>>((float4*)d_out);
}